// round 15
// baseline (speedup 1.0000x reference)
#include <cuda_runtime.h>
#include <cuda_fp16.h>
#include <cstdint>
#include <cstddef>

#define R_DIM 256
#define C_DIM 256
#define E_DIM 768
#define H_HEADS 12
#define DH 64
#define TOK (R_DIM * C_DIM)
#define SCALE 0.0078125f
#define KDIM 768

#define PROJ_ELEMS ((size_t)TOK * E_DIM)
#define W_ELEMS ((size_t)H_HEADS * C_DIM * C_DIM)
#define WSZ ((size_t)E_DIM * E_DIM)

__device__ __half g_Ah[PROJ_ELEMS];   // x fp16; later reused for Ctx fp16
__device__ __half g_Qh[PROJ_ELEMS];
__device__ __half g_Kh[PROJ_ELEMS];
__device__ __half g_Vh[PROJ_ELEMS];
__device__ __half g_Wq4[4 * WSZ];     // weights fp16
__device__ __half g_Ph[W_ELEMS];
__device__ float g_Wpart[96 * 65536];

extern __shared__ char dynsmem[];

// ---------------- helpers ----------------
__device__ __forceinline__ uint32_t smem_u32(const void* p) {
    uint32_t a;
    asm("{ .reg .u64 t; cvta.to.shared.u64 t, %1; cvt.u32.u64 %0, t; }" : "=r"(a) : "l"(p));
    return a;
}
__device__ __forceinline__ void cp16(uint32_t dst, const void* src) {
    asm volatile("cp.async.cg.shared.global [%0], [%1], 16;\n" :: "r"(dst), "l"(src));
}
__device__ __forceinline__ void hmma(float* c, const uint32_t* a, const uint32_t* b) {
    asm volatile(
        "mma.sync.aligned.m16n8k16.row.col.f32.f16.f16.f32 "
        "{%0,%1,%2,%3}, {%4,%5,%6,%7}, {%8,%9}, {%0,%1,%2,%3};"
        : "+f"(c[0]), "+f"(c[1]), "+f"(c[2]), "+f"(c[3])
        : "r"(a[0]), "r"(a[1]), "r"(a[2]), "r"(a[3]), "r"(b[0]), "r"(b[1]));
}
__device__ __forceinline__ void ldm4(uint32_t* r, uint32_t a) {
    asm volatile("ldmatrix.sync.aligned.m8n8.x4.shared.b16 {%0,%1,%2,%3}, [%4];"
        : "=r"(r[0]), "=r"(r[1]), "=r"(r[2]), "=r"(r[3]) : "r"(a));
}
__device__ __forceinline__ void ldm4t(uint32_t* r, uint32_t a) {
    asm volatile("ldmatrix.sync.aligned.m8n8.x4.trans.shared.b16 {%0,%1,%2,%3}, [%4];"
        : "=r"(r[0]), "=r"(r[1]), "=r"(r[2]), "=r"(r[3]) : "r"(a));
}
__device__ __forceinline__ uint32_t pack_h(float v0, float v1) {
    __half h0 = __float2half_rn(v0), h1 = __float2half_rn(v1);
    return (uint32_t)*(unsigned short*)&h0 | ((uint32_t)*(unsigned short*)&h1 << 16);
}

// ---------------- fp32 -> fp16 converts ----------------
__global__ __launch_bounds__(256) void split1_kernel(
    const float* __restrict__ src, __half* __restrict__ hi, int n)
{
    int i = (blockIdx.x * 256 + threadIdx.x) * 4;
    if (i >= n) return;
    float4 v = *(const float4*)(src + i);
    *(uint2*)(hi + i) = make_uint2(pack_h(v.x, v.y), pack_h(v.z, v.w));
}
__global__ __launch_bounds__(256) void split4w_kernel(
    const float* __restrict__ w0, const float* __restrict__ w1,
    const float* __restrict__ w2, const float* __restrict__ w3,
    __half* __restrict__ hi)
{
    const float* src = blockIdx.y == 0 ? w0 : (blockIdx.y == 1 ? w1
                      : (blockIdx.y == 2 ? w2 : w3));
    __half* dst = hi + (size_t)blockIdx.y * WSZ;
    int i = (blockIdx.x * 256 + threadIdx.x) * 4;
    if (i >= (int)WSZ) return;
    float4 v = *(const float4*)(src + i);
    *(uint2*)(dst + i) = make_uint2(pack_h(v.x, v.y), pack_h(v.z, v.w));
}

// ---------------------------------------------------------------------------
// Projection GEMMs: CTA 128x128, 256 threads, 8 warps (2m x 4n, warp 64x32),
// BK=32, 3-stage cp.async, 1 sync/chunk, 3 CTAs/SM (6 warps/SMSP).
// LDS traffic 192 B/hmma (75% of crossbar budget at HMMA rt8).
// ---------------------------------------------------------------------------
#define ST_AH 0
#define ST_BH 8192
#define STAGE 16384
#define GEMM_SMEM (3 * STAGE)          // 49152
#define NCH (KDIM / 32)                // 24

// Fused QKV: grid.x = 18; wsel = x/6 picks {Wq,Wk,Wv}; fp16 out.
__global__ __launch_bounds__(256, 3) void gemm_qkv(
    const __half* __restrict__ Ahp, const __half* __restrict__ Whp,
    const float* __restrict__ bq, const float* __restrict__ bk,
    const float* __restrict__ bv,
    __half* __restrict__ Qo, __half* __restrict__ Ko, __half* __restrict__ Vo)
{
    const int wsel = blockIdx.x / 6;
    const int n0 = (blockIdx.x % 6) * 128;
    const __half* Bhp = Whp + (size_t)wsel * WSZ;
    const float* bias = wsel == 0 ? bq : (wsel == 1 ? bk : bv);
    __half* Oh = wsel == 0 ? Qo : (wsel == 1 ? Ko : Vo);

    const uint32_t sb = smem_u32(dynsmem);
    const int tid = threadIdx.x, wid = tid >> 5, lane = tid & 31;
    const int gid = lane >> 2, tig = lane & 3;
    const int q = lane >> 3, r8 = lane & 7, qlo = q & 1, qhi = q >> 1;
    const int wm = (wid & 1) * 64, wn = (wid >> 1) * 32;
    const int m0 = blockIdx.y * 128;

    int aoff[4], axor[4], boff[2], bxor[2];
#pragma unroll
    for (int mt = 0; mt < 4; mt++) {
        int rr = wm + mt * 16 + qlo * 8 + r8;
        aoff[mt] = rr * 64; axor[mt] = (rr >> 1) & 3;
    }
#pragma unroll
    for (int p = 0; p < 2; p++) {
        int rr = wn + p * 16 + qlo * 8 + r8;
        boff[p] = rr * 64; bxor[p] = (rr >> 1) & 3;
    }

    float acc[4][4][4];
#pragma unroll
    for (int mt = 0; mt < 4; mt++)
#pragma unroll
        for (int nt = 0; nt < 4; nt++)
#pragma unroll
            for (int e = 0; e < 4; e++) acc[mt][nt][e] = 0.0f;

    auto load_chunk = [&](int c) {
        const uint32_t stg = sb + (uint32_t)(c % 3) * STAGE;
        const int k0 = c * 32;
#pragma unroll
        for (int t = 0; t < 4; t++) {
            int task = tid + t * 256;            // 0..1023
            int isB = task >> 9, r2 = task & 511;
            int row = r2 >> 2, g = r2 & 3;
            uint32_t so = (uint32_t)(row * 64 + ((g ^ ((row >> 1) & 3)) << 4));
            if (!isB) cp16(stg + ST_AH + so, Ahp + (size_t)(m0 + row) * KDIM + k0 + g * 8);
            else      cp16(stg + ST_BH + so, Bhp + (size_t)(n0 + row) * KDIM + k0 + g * 8);
        }
        asm volatile("cp.async.commit_group;\n" ::: "memory");
    };

    load_chunk(0); load_chunk(1);

    for (int c = 0; c < NCH; c++) {
        const uint32_t stg = sb + (uint32_t)(c % 3) * STAGE;
        if (c < NCH - 1) asm volatile("cp.async.wait_group 1;\n" ::: "memory");
        else             asm volatile("cp.async.wait_group 0;\n" ::: "memory");
        __syncthreads();
        if (c + 2 < NCH) load_chunk(c + 2);

#pragma unroll
        for (int ks = 0; ks < 2; ks++) {
            const int g = ks * 2 + qhi;
            uint32_t a[4], b[4][2], t4[4];
#pragma unroll
            for (int p = 0; p < 2; p++) {
                ldm4(t4, stg + ST_BH + boff[p] + (uint32_t)((g ^ bxor[p]) << 4));
                b[2*p][0] = t4[0]; b[2*p+1][0] = t4[1]; b[2*p][1] = t4[2]; b[2*p+1][1] = t4[3];
            }
#pragma unroll
            for (int mt = 0; mt < 4; mt++) {
                ldm4(a, stg + ST_AH + aoff[mt] + (uint32_t)((g ^ axor[mt]) << 4));
#pragma unroll
                for (int nt = 0; nt < 4; nt++) hmma(acc[mt][nt], a, b[nt]);
            }
        }
    }

#pragma unroll
    for (int mt = 0; mt < 4; mt++) {
        const int row = m0 + wm + mt * 16 + gid;
#pragma unroll
        for (int nt = 0; nt < 4; nt++) {
            const int col = n0 + wn + nt * 8 + tig * 2;
            const float bb0 = __ldg(bias + col), bb1 = __ldg(bias + col + 1);
            *(uint32_t*)(Oh + (size_t)row * E_DIM + col) =
                pack_h(acc[mt][nt][0] + bb0, acc[mt][nt][1] + bb1);
            *(uint32_t*)(Oh + (size_t)(row + 8) * E_DIM + col) =
                pack_h(acc[mt][nt][2] + bb0, acc[mt][nt][3] + bb1);
        }
    }
}

// Output projection: f32 out, same structure.
__global__ __launch_bounds__(256, 3) void gemm_out(
    const __half* __restrict__ Ahp, const __half* __restrict__ Bhp,
    const float* __restrict__ bias, float* __restrict__ Cf)
{
    const uint32_t sb = smem_u32(dynsmem);
    const int tid = threadIdx.x, wid = tid >> 5, lane = tid & 31;
    const int gid = lane >> 2, tig = lane & 3;
    const int q = lane >> 3, r8 = lane & 7, qlo = q & 1, qhi = q >> 1;
    const int wm = (wid & 1) * 64, wn = (wid >> 1) * 32;
    const int m0 = blockIdx.y * 128, n0 = blockIdx.x * 128;

    int aoff[4], axor[4], boff[2], bxor[2];
#pragma unroll
    for (int mt = 0; mt < 4; mt++) {
        int rr = wm + mt * 16 + qlo * 8 + r8;
        aoff[mt] = rr * 64; axor[mt] = (rr >> 1) & 3;
    }
#pragma unroll
    for (int p = 0; p < 2; p++) {
        int rr = wn + p * 16 + qlo * 8 + r8;
        boff[p] = rr * 64; bxor[p] = (rr >> 1) & 3;
    }

    float acc[4][4][4];
#pragma unroll
    for (int mt = 0; mt < 4; mt++)
#pragma unroll
        for (int nt = 0; nt < 4; nt++)
#pragma unroll
            for (int e = 0; e < 4; e++) acc[mt][nt][e] = 0.0f;

    auto load_chunk = [&](int c) {
        const uint32_t stg = sb + (uint32_t)(c % 3) * STAGE;
        const int k0 = c * 32;
#pragma unroll
        for (int t = 0; t < 4; t++) {
            int task = tid + t * 256;
            int isB = task >> 9, r2 = task & 511;
            int row = r2 >> 2, g = r2 & 3;
            uint32_t so = (uint32_t)(row * 64 + ((g ^ ((row >> 1) & 3)) << 4));
            if (!isB) cp16(stg + ST_AH + so, Ahp + (size_t)(m0 + row) * KDIM + k0 + g * 8);
            else      cp16(stg + ST_BH + so, Bhp + (size_t)(n0 + row) * KDIM + k0 + g * 8);
        }
        asm volatile("cp.async.commit_group;\n" ::: "memory");
    };

    load_chunk(0); load_chunk(1);

    for (int c = 0; c < NCH; c++) {
        const uint32_t stg = sb + (uint32_t)(c % 3) * STAGE;
        if (c < NCH - 1) asm volatile("cp.async.wait_group 1;\n" ::: "memory");
        else             asm volatile("cp.async.wait_group 0;\n" ::: "memory");
        __syncthreads();
        if (c + 2 < NCH) load_chunk(c + 2);

#pragma unroll
        for (int ks = 0; ks < 2; ks++) {
            const int g = ks * 2 + qhi;
            uint32_t a[4], b[4][2], t4[4];
#pragma unroll
            for (int p = 0; p < 2; p++) {
                ldm4(t4, stg + ST_BH + boff[p] + (uint32_t)((g ^ bxor[p]) << 4));
                b[2*p][0] = t4[0]; b[2*p+1][0] = t4[1]; b[2*p][1] = t4[2]; b[2*p+1][1] = t4[3];
            }
#pragma unroll
            for (int mt = 0; mt < 4; mt++) {
                ldm4(a, stg + ST_AH + aoff[mt] + (uint32_t)((g ^ axor[mt]) << 4));
#pragma unroll
                for (int nt = 0; nt < 4; nt++) hmma(acc[mt][nt], a, b[nt]);
            }
        }
    }

#pragma unroll
    for (int mt = 0; mt < 4; mt++) {
        const int row = m0 + wm + mt * 16 + gid;
#pragma unroll
        for (int nt = 0; nt < 4; nt++) {
            const int col = n0 + wn + nt * 8 + tig * 2;
            const float bb0 = __ldg(bias + col), bb1 = __ldg(bias + col + 1);
            *(float2*)(Cf + (size_t)row * E_DIM + col) =
                make_float2(acc[mt][nt][0] + bb0, acc[mt][nt][1] + bb1);
            *(float2*)(Cf + (size_t)(row + 8) * E_DIM + col) =
                make_float2(acc[mt][nt][2] + bb0, acc[mt][nt][3] + bb1);
        }
    }
}

// ---------------------------------------------------------------------------
// Scores (fp16): R12 proven config — 256 threads, warp 64x32, BK=64.
// ---------------------------------------------------------------------------
#define SC_AH 0
#define SC_BH 16384
#define SC_STAGE 32768
#define SC_SMEM (3 * SC_STAGE)        // 98304

__global__ __launch_bounds__(256, 2) void scores_hmma(
    const __half* __restrict__ Qh, const __half* __restrict__ Kh,
    float* __restrict__ Wp)
{
    const uint32_t sb = smem_u32(dynsmem);
    const int tid = threadIdx.x, wid = tid >> 5, lane = tid & 31;
    const int gid = lane >> 2, tig = lane & 3;
    const int q = lane >> 3, r8 = lane & 7, qlo = q & 1, qhi = q >> 1;
    const int wm = (wid & 1) * 64, wn = (wid >> 1) * 32;
    const int h = blockIdx.z >> 3, rs = blockIdx.z & 7;
    const int i0 = blockIdx.x * 128, j0 = blockIdx.y * 128;
    const int r_lo = rs * 32;

    int aoff[4], axor[4], boff[2], bxor[2];
#pragma unroll
    for (int mt = 0; mt < 4; mt++) {
        int rr = wm + mt * 16 + qlo * 8 + r8;
        aoff[mt] = rr * 128; axor[mt] = rr & 7;
    }
#pragma unroll
    for (int p = 0; p < 2; p++) {
        int rr = wn + p * 16 + qlo * 8 + r8;
        boff[p] = rr * 128; bxor[p] = rr & 7;
    }

    float acc[4][4][4];
#pragma unroll
    for (int mt = 0; mt < 4; mt++)
#pragma unroll
        for (int nt = 0; nt < 4; nt++)
#pragma unroll
            for (int e = 0; e < 4; e++) acc[mt][nt][e] = 0.0f;

    auto load_chunk = [&](int c) {
        const uint32_t stg = sb + (uint32_t)(c % 3) * SC_STAGE;
        const int r = r_lo + c;
#pragma unroll
        for (int t = 0; t < 8; t++) {
            int task = tid + t * 256;
            int isB = task >> 10, r2 = task & 1023;
            int row = r2 >> 3, g = r2 & 7;
            uint32_t so = (uint32_t)(row * 128 + ((g ^ (row & 7)) << 4));
            if (!isB)
                cp16(stg + SC_AH + so,
                     Qh + (size_t)(r * 256 + i0 + row) * E_DIM + h * DH + g * 8);
            else
                cp16(stg + SC_BH + so,
                     Kh + (size_t)(r * 256 + j0 + row) * E_DIM + h * DH + g * 8);
        }
        asm volatile("cp.async.commit_group;\n" ::: "memory");
    };

    load_chunk(0); load_chunk(1);

    for (int c = 0; c < 32; c++) {
        const uint32_t stg = sb + (uint32_t)(c % 3) * SC_STAGE;
        if (c < 31) asm volatile("cp.async.wait_group 1;\n" ::: "memory");
        else        asm volatile("cp.async.wait_group 0;\n" ::: "memory");
        __syncthreads();
        if (c + 2 < 32) load_chunk(c + 2);
#pragma unroll
        for (int ks = 0; ks < 4; ks++) {
            const int g = ks * 2 + qhi;
            uint32_t a[4], b[4][2], t4[4];
#pragma unroll
            for (int p = 0; p < 2; p++) {
                ldm4(t4, stg + SC_BH + boff[p] + (uint32_t)((g ^ bxor[p]) << 4));
                b[2*p][0] = t4[0]; b[2*p+1][0] = t4[1]; b[2*p][1] = t4[2]; b[2*p+1][1] = t4[3];
            }
#pragma unroll
            for (int mt = 0; mt < 4; mt++) {
                ldm4(a, stg + SC_AH + aoff[mt] + (uint32_t)((g ^ axor[mt]) << 4));
#pragma unroll
                for (int nt = 0; nt < 4; nt++) hmma(acc[mt][nt], a, b[nt]);
            }
        }
    }

    float* base = Wp + (size_t)blockIdx.z * 65536;
#pragma unroll
    for (int mt = 0; mt < 4; mt++) {
        const int i = i0 + wm + mt * 16 + gid;
#pragma unroll
        for (int nt = 0; nt < 4; nt++) {
            const int j = j0 + wn + nt * 8 + tig * 2;
            *(float2*)(base + (size_t)i * 256 + j)       = make_float2(acc[mt][nt][0], acc[mt][nt][1]);
            *(float2*)(base + (size_t)(i + 8) * 256 + j) = make_float2(acc[mt][nt][2], acc[mt][nt][3]);
        }
    }
}

// ---------------------------------------------------------------------------
// Reduce partials + SCALE + softmax (unchanged)
// ---------------------------------------------------------------------------
__global__ __launch_bounds__(256) void softmax_reduce(
    const float* __restrict__ Wp, float* __restrict__ P,
    __half* __restrict__ Ph)
{
    __shared__ float red[8];
    const int row = blockIdx.x;
    const int h = row >> 8;
    const int tid = threadIdx.x;

    float v = 0.0f;
#pragma unroll
    for (int rs = 0; rs < 8; rs++)
        v += Wp[((size_t)(h * 8 + rs)) * 65536 + (size_t)(row & 255) * 256 + tid];
    v *= SCALE;

    float m = v;
#pragma unroll
    for (int o = 16; o > 0; o >>= 1) m = fmaxf(m, __shfl_xor_sync(0xffffffffu, m, o));
    if ((tid & 31) == 0) red[tid >> 5] = m;
    __syncthreads();
    float m_all = red[0];
#pragma unroll
    for (int w = 1; w < 8; w++) m_all = fmaxf(m_all, red[w]);
    const float e = __expf(v - m_all);
    float s = e;
#pragma unroll
    for (int o = 16; o > 0; o >>= 1) s += __shfl_xor_sync(0xffffffffu, s, o);
    __syncthreads();
    if ((tid & 31) == 0) red[tid >> 5] = s;
    __syncthreads();
    float s_all = 0.0f;
#pragma unroll
    for (int w = 0; w < 8; w++) s_all += red[w];

    const float p = e / s_all;
    const size_t idx = (size_t)row * 256 + tid;
    P[idx] = p;
    Ph[idx] = __float2half_rn(p);
}

// ---------------------------------------------------------------------------
// Context (fp16), r-blocked x8; occupancy raised to 4 CTAs/SM.
// ---------------------------------------------------------------------------
#define CT_PH 0
#define CT_VH 8192
#define CT_STAGE 12288
#define CT_SMEM (2 * CT_STAGE)        // 24576

__global__ __launch_bounds__(256, 4) void context_hmma(
    const __half* __restrict__ Ph, const __half* __restrict__ Vh,
    __half* __restrict__ Oh)
{
    const uint32_t sb = smem_u32(dynsmem);
    const int tid = threadIdx.x, wid = tid >> 5, lane = tid & 31;
    const int gid = lane >> 2, tig = lane & 3;
    const int q = lane >> 3, r8 = lane & 7, qlo = q & 1, qhi = q >> 1;
    const int wmi = (wid >> 1) * 32, wnd = (wid & 1) * 32;
    const int i0 = blockIdx.x * 128, r_base = blockIdx.y * 8, h = blockIdx.z;

    int aoff[2], axor[2];
#pragma unroll
    for (int mt = 0; mt < 2; mt++) {
        int rr = wmi + mt * 16 + qlo * 8 + r8;
        aoff[mt] = rr * 64; axor[mt] = (rr >> 1) & 3;
    }
    int gB[2];
#pragma unroll
    for (int p = 0; p < 2; p++) gB[p] = (wnd >> 3) + p * 2 + qhi;
    const int jbase = qlo * 8 + r8;

    float acc[2][4][4];
#pragma unroll
    for (int mt = 0; mt < 2; mt++)
#pragma unroll
        for (int nt = 0; nt < 4; nt++)
#pragma unroll
            for (int e = 0; e < 4; e++) acc[mt][nt][e] = 0.0f;

    auto load_chunk = [&](int cc) {
        const uint32_t stg = sb + (uint32_t)(cc & 1) * CT_STAGE;
        const int j0 = (cc & 7) * 32;
        const int r = r_base + (cc >> 3);
#pragma unroll
        for (int t = 0; t < 3; t++) {
            int task = tid + t * 256;
            if (task < 512) {
                int row = task >> 2, g = task & 3;
                cp16(stg + CT_PH + (uint32_t)(row * 64 + ((g ^ ((row >> 1) & 3)) << 4)),
                     Ph + (size_t)h * 65536 + (size_t)(i0 + row) * 256 + j0 + g * 8);
            } else {
                int t2 = task - 512;
                int row = t2 >> 3, g = t2 & 7;
                cp16(stg + CT_VH + (uint32_t)(row * 128 + ((g ^ (row & 7)) << 4)),
                     Vh + (size_t)(r * 256 + j0 + row) * E_DIM + h * DH + g * 8);
            }
        }
        asm volatile("cp.async.commit_group;\n" ::: "memory");
    };

    load_chunk(0); load_chunk(1);

    for (int cc = 0; cc < 64; cc++) {
        const uint32_t stg = sb + (uint32_t)(cc & 1) * CT_STAGE;
        if (cc == 63) asm volatile("cp.async.wait_group 0;\n" ::: "memory");
        else          asm volatile("cp.async.wait_group 1;\n" ::: "memory");
        __syncthreads();
#pragma unroll
        for (int ks = 0; ks < 2; ks++) {
            const int ga = ks * 2 + qhi;
            const int jrow = ks * 16 + jbase;
            uint32_t a[2][4], b[4][2], t4[4];
#pragma unroll
            for (int p = 0; p < 2; p++) {
                ldm4t(t4, stg + CT_VH + (uint32_t)(jrow * 128 + ((gB[p] ^ (jrow & 7)) << 4)));
                b[2*p][0] = t4[0]; b[2*p][1] = t4[1]; b[2*p+1][0] = t4[2]; b[2*p+1][1] = t4[3];
            }
#pragma unroll
            for (int mt = 0; mt < 2; mt++)
                ldm4(a[mt], stg + CT_PH + aoff[mt] + (uint32_t)((ga ^ axor[mt]) << 4));
#pragma unroll
            for (int mt = 0; mt < 2; mt++)
#pragma unroll
                for (int nt = 0; nt < 4; nt++) hmma(acc[mt][nt], a[mt], b[nt]);
        }

        if ((cc & 7) == 7) {
            const int r = r_base + (cc >> 3);
#pragma unroll
            for (int mt = 0; mt < 2; mt++) {
                const int row_i = i0 + wmi + mt * 16 + gid;
#pragma unroll
                for (int nt = 0; nt < 4; nt++) {
                    const int col = wnd + nt * 8 + tig * 2;
                    size_t i0b = (size_t)(r * 256 + row_i) * E_DIM + h * DH + col;
                    size_t i1b = (size_t)(r * 256 + row_i + 8) * E_DIM + h * DH + col;
                    *(uint32_t*)(Oh + i0b) = pack_h(acc[mt][nt][0], acc[mt][nt][1]);
                    *(uint32_t*)(Oh + i1b) = pack_h(acc[mt][nt][2], acc[mt][nt][3]);
#pragma unroll
                    for (int e = 0; e < 4; e++) acc[mt][nt][e] = 0.0f;
                }
            }
        }
        __syncthreads();
        if (cc + 2 < 64) load_chunk(cc + 2);
    }
}

// ---------------- launch ----------------
extern "C" void kernel_launch(void* const* d_in, const int* in_sizes, int n_in,
                              void* d_out, int out_size)
{
    const float* x  = (const float*)d_in[0];
    const float* Wq = (const float*)d_in[1];
    const float* bq = (const float*)d_in[2];
    const float* Wk = (const float*)d_in[3];
    const float* bk = (const float*)d_in[4];
    const float* Wv = (const float*)d_in[5];
    const float* bv = (const float*)d_in[6];
    const float* Wo = (const float*)d_in[7];
    const float* bo = (const float*)d_in[8];

    float* out_y = (float*)d_out;
    float* out_p = (float*)d_out + PROJ_ELEMS;

    __half *Ah, *Qh, *Kh, *Vh, *Wh, *Ph;
    float* Wp;
    cudaGetSymbolAddress((void**)&Ah, g_Ah);
    cudaGetSymbolAddress((void**)&Qh, g_Qh);
    cudaGetSymbolAddress((void**)&Kh, g_Kh);
    cudaGetSymbolAddress((void**)&Vh, g_Vh);
    cudaGetSymbolAddress((void**)&Wh, g_Wq4);
    cudaGetSymbolAddress((void**)&Ph, g_Ph);
    cudaGetSymbolAddress((void**)&Wp, g_Wpart);

    cudaFuncSetAttribute(gemm_qkv,     cudaFuncAttributeMaxDynamicSharedMemorySize, GEMM_SMEM);
    cudaFuncSetAttribute(gemm_out,     cudaFuncAttributeMaxDynamicSharedMemorySize, GEMM_SMEM);
    cudaFuncSetAttribute(scores_hmma,  cudaFuncAttributeMaxDynamicSharedMemorySize, SC_SMEM);
    cudaFuncSetAttribute(context_hmma, cudaFuncAttributeMaxDynamicSharedMemorySize, CT_SMEM);

    const int nx = (int)PROJ_ELEMS, nw = (int)WSZ;
    split1_kernel<<<nx / 1024, 256>>>(x, Ah, nx);
    split4w_kernel<<<dim3(nw / 1024, 4), 256>>>(Wq, Wk, Wv, Wo, Wh);

    gemm_qkv<<<dim3(18, TOK / 128), 256, GEMM_SMEM>>>(Ah, Wh, bq, bk, bv, Qh, Kh, Vh);

    scores_hmma<<<dim3(2, 2, 96), 256, SC_SMEM>>>(Qh, Kh, Wp);
    softmax_reduce<<<H_HEADS * C_DIM, 256>>>(Wp, out_p, Ph);
    context_hmma<<<dim3(2, 32, 12), 256, CT_SMEM>>>(Ph, Vh, Ah);

    gemm_out<<<dim3(6, TOK / 128), 256, GEMM_SMEM>>>(Ah, Wh + 3 * WSZ, bo, out_y);
}

// round 16
// speedup vs baseline: 1.3257x; 1.3257x over previous
#include <cuda_runtime.h>
#include <cuda_fp16.h>
#include <cstdint>
#include <cstddef>

#define R_DIM 256
#define C_DIM 256
#define E_DIM 768
#define H_HEADS 12
#define DH 64
#define TOK (R_DIM * C_DIM)
#define SCALE 0.0078125f
#define KDIM 768

#define PROJ_ELEMS ((size_t)TOK * E_DIM)
#define W_ELEMS ((size_t)H_HEADS * C_DIM * C_DIM)
#define WSZ ((size_t)E_DIM * E_DIM)

__device__ __half g_Ah[PROJ_ELEMS];   // x fp16; later reused for Ctx fp16
__device__ __half g_Qh[PROJ_ELEMS];
__device__ __half g_Kh[PROJ_ELEMS];
__device__ __half g_Vh[PROJ_ELEMS];
__device__ __half g_Wq4[4 * WSZ];     // weights fp16
__device__ __half g_Ph[W_ELEMS];
__device__ float g_Wpart[96 * 65536];

extern __shared__ char dynsmem[];

// ---------------- helpers ----------------
__device__ __forceinline__ uint32_t smem_u32(const void* p) {
    uint32_t a;
    asm("{ .reg .u64 t; cvta.to.shared.u64 t, %1; cvt.u32.u64 %0, t; }" : "=r"(a) : "l"(p));
    return a;
}
__device__ __forceinline__ void cp16(uint32_t dst, const void* src) {
    asm volatile("cp.async.cg.shared.global [%0], [%1], 16;\n" :: "r"(dst), "l"(src));
}
__device__ __forceinline__ void hmma(float* c, const uint32_t* a, const uint32_t* b) {
    asm volatile(
        "mma.sync.aligned.m16n8k16.row.col.f32.f16.f16.f32 "
        "{%0,%1,%2,%3}, {%4,%5,%6,%7}, {%8,%9}, {%0,%1,%2,%3};"
        : "+f"(c[0]), "+f"(c[1]), "+f"(c[2]), "+f"(c[3])
        : "r"(a[0]), "r"(a[1]), "r"(a[2]), "r"(a[3]), "r"(b[0]), "r"(b[1]));
}
__device__ __forceinline__ void ldm4(uint32_t* r, uint32_t a) {
    asm volatile("ldmatrix.sync.aligned.m8n8.x4.shared.b16 {%0,%1,%2,%3}, [%4];"
        : "=r"(r[0]), "=r"(r[1]), "=r"(r[2]), "=r"(r[3]) : "r"(a));
}
__device__ __forceinline__ void ldm4t(uint32_t* r, uint32_t a) {
    asm volatile("ldmatrix.sync.aligned.m8n8.x4.trans.shared.b16 {%0,%1,%2,%3}, [%4];"
        : "=r"(r[0]), "=r"(r[1]), "=r"(r[2]), "=r"(r[3]) : "r"(a));
}
__device__ __forceinline__ uint32_t pack_h(float v0, float v1) {
    __half h0 = __float2half_rn(v0), h1 = __float2half_rn(v1);
    return (uint32_t)*(unsigned short*)&h0 | ((uint32_t)*(unsigned short*)&h1 << 16);
}

// ---------------- fp32 -> fp16 converts ----------------
__global__ __launch_bounds__(256) void split1_kernel(
    const float* __restrict__ src, __half* __restrict__ hi, int n)
{
    int i = (blockIdx.x * 256 + threadIdx.x) * 4;
    if (i >= n) return;
    float4 v = *(const float4*)(src + i);
    *(uint2*)(hi + i) = make_uint2(pack_h(v.x, v.y), pack_h(v.z, v.w));
}
__global__ __launch_bounds__(256) void split4w_kernel(
    const float* __restrict__ w0, const float* __restrict__ w1,
    const float* __restrict__ w2, const float* __restrict__ w3,
    __half* __restrict__ hi)
{
    const float* src = blockIdx.y == 0 ? w0 : (blockIdx.y == 1 ? w1
                      : (blockIdx.y == 2 ? w2 : w3));
    __half* dst = hi + (size_t)blockIdx.y * WSZ;
    int i = (blockIdx.x * 256 + threadIdx.x) * 4;
    if (i >= (int)WSZ) return;
    float4 v = *(const float4*)(src + i);
    *(uint2*)(dst + i) = make_uint2(pack_h(v.x, v.y), pack_h(v.z, v.w));
}

// ---------------------------------------------------------------------------
// Projection GEMMs (R13 proven): CTA 128x128, 512 threads (16 warps, 4m x 4n,
// warp 32x32), BK=32, 3-stage cp.async, 1 sync/chunk, 2 CTAs/SM (8 w/SMSP).
// ---------------------------------------------------------------------------
#define ST_AH 0
#define ST_BH 8192
#define STAGE 16384
#define GEMM_SMEM (3 * STAGE)          // 49152
#define NCH (KDIM / 32)                // 24

// Fused QKV: grid.x = 18; wsel = x/6 picks {Wq,Wk,Wv}; fp16 out.
__global__ __launch_bounds__(512, 2) void gemm_qkv(
    const __half* __restrict__ Ahp, const __half* __restrict__ Whp,
    const float* __restrict__ bq, const float* __restrict__ bk,
    const float* __restrict__ bv,
    __half* __restrict__ Qo, __half* __restrict__ Ko, __half* __restrict__ Vo)
{
    const int wsel = blockIdx.x / 6;
    const int n0 = (blockIdx.x % 6) * 128;
    const __half* Bhp = Whp + (size_t)wsel * WSZ;
    const float* bias = wsel == 0 ? bq : (wsel == 1 ? bk : bv);
    __half* Oh = wsel == 0 ? Qo : (wsel == 1 ? Ko : Vo);

    const uint32_t sb = smem_u32(dynsmem);
    const int tid = threadIdx.x, wid = tid >> 5, lane = tid & 31;
    const int gid = lane >> 2, tig = lane & 3;
    const int q = lane >> 3, r8 = lane & 7, qlo = q & 1, qhi = q >> 1;
    const int wm = (wid & 3) * 32, wn = (wid >> 2) * 32;
    const int m0 = blockIdx.y * 128;

    int aoff[2], axor[2], boff[2], bxor[2];
#pragma unroll
    for (int mt = 0; mt < 2; mt++) {
        int rr = wm + mt * 16 + qlo * 8 + r8;
        aoff[mt] = rr * 64; axor[mt] = (rr >> 1) & 3;
    }
#pragma unroll
    for (int p = 0; p < 2; p++) {
        int rr = wn + p * 16 + qlo * 8 + r8;
        boff[p] = rr * 64; bxor[p] = (rr >> 1) & 3;
    }

    float acc[2][4][4];
#pragma unroll
    for (int mt = 0; mt < 2; mt++)
#pragma unroll
        for (int nt = 0; nt < 4; nt++)
#pragma unroll
            for (int e = 0; e < 4; e++) acc[mt][nt][e] = 0.0f;

    auto load_chunk = [&](int c) {
        const uint32_t stg = sb + (uint32_t)(c % 3) * STAGE;
        const int k0 = c * 32;
#pragma unroll
        for (int t = 0; t < 2; t++) {
            int task = tid + t * 512;            // 0..1023
            int isB = task >> 9, r2 = task & 511;
            int row = r2 >> 2, g = r2 & 3;
            uint32_t so = (uint32_t)(row * 64 + ((g ^ ((row >> 1) & 3)) << 4));
            if (!isB) cp16(stg + ST_AH + so, Ahp + (size_t)(m0 + row) * KDIM + k0 + g * 8);
            else      cp16(stg + ST_BH + so, Bhp + (size_t)(n0 + row) * KDIM + k0 + g * 8);
        }
        asm volatile("cp.async.commit_group;\n" ::: "memory");
    };

    load_chunk(0); load_chunk(1);

    for (int c = 0; c < NCH; c++) {
        const uint32_t stg = sb + (uint32_t)(c % 3) * STAGE;
        if (c < NCH - 1) asm volatile("cp.async.wait_group 1;\n" ::: "memory");
        else             asm volatile("cp.async.wait_group 0;\n" ::: "memory");
        __syncthreads();
        if (c + 2 < NCH) load_chunk(c + 2);

#pragma unroll
        for (int ks = 0; ks < 2; ks++) {
            const int g = ks * 2 + qhi;
            uint32_t a[2][4], b[4][2], t4[4];
#pragma unroll
            for (int p = 0; p < 2; p++) {
                ldm4(t4, stg + ST_BH + boff[p] + (uint32_t)((g ^ bxor[p]) << 4));
                b[2*p][0] = t4[0]; b[2*p+1][0] = t4[1]; b[2*p][1] = t4[2]; b[2*p+1][1] = t4[3];
            }
#pragma unroll
            for (int mt = 0; mt < 2; mt++)
                ldm4(a[mt], stg + ST_AH + aoff[mt] + (uint32_t)((g ^ axor[mt]) << 4));
#pragma unroll
            for (int mt = 0; mt < 2; mt++)
#pragma unroll
                for (int nt = 0; nt < 4; nt++) hmma(acc[mt][nt], a[mt], b[nt]);
        }
    }

#pragma unroll
    for (int mt = 0; mt < 2; mt++) {
        const int row = m0 + wm + mt * 16 + gid;
#pragma unroll
        for (int nt = 0; nt < 4; nt++) {
            const int col = n0 + wn + nt * 8 + tig * 2;
            const float bb0 = __ldg(bias + col), bb1 = __ldg(bias + col + 1);
            *(uint32_t*)(Oh + (size_t)row * E_DIM + col) =
                pack_h(acc[mt][nt][0] + bb0, acc[mt][nt][1] + bb1);
            *(uint32_t*)(Oh + (size_t)(row + 8) * E_DIM + col) =
                pack_h(acc[mt][nt][2] + bb0, acc[mt][nt][3] + bb1);
        }
    }
}

// Output projection: f32 out, same 512-thread structure.
__global__ __launch_bounds__(512, 2) void gemm_out(
    const __half* __restrict__ Ahp, const __half* __restrict__ Bhp,
    const float* __restrict__ bias, float* __restrict__ Cf)
{
    const uint32_t sb = smem_u32(dynsmem);
    const int tid = threadIdx.x, wid = tid >> 5, lane = tid & 31;
    const int gid = lane >> 2, tig = lane & 3;
    const int q = lane >> 3, r8 = lane & 7, qlo = q & 1, qhi = q >> 1;
    const int wm = (wid & 3) * 32, wn = (wid >> 2) * 32;
    const int m0 = blockIdx.y * 128, n0 = blockIdx.x * 128;

    int aoff[2], axor[2], boff[2], bxor[2];
#pragma unroll
    for (int mt = 0; mt < 2; mt++) {
        int rr = wm + mt * 16 + qlo * 8 + r8;
        aoff[mt] = rr * 64; axor[mt] = (rr >> 1) & 3;
    }
#pragma unroll
    for (int p = 0; p < 2; p++) {
        int rr = wn + p * 16 + qlo * 8 + r8;
        boff[p] = rr * 64; bxor[p] = (rr >> 1) & 3;
    }

    float acc[2][4][4];
#pragma unroll
    for (int mt = 0; mt < 2; mt++)
#pragma unroll
        for (int nt = 0; nt < 4; nt++)
#pragma unroll
            for (int e = 0; e < 4; e++) acc[mt][nt][e] = 0.0f;

    auto load_chunk = [&](int c) {
        const uint32_t stg = sb + (uint32_t)(c % 3) * STAGE;
        const int k0 = c * 32;
#pragma unroll
        for (int t = 0; t < 2; t++) {
            int task = tid + t * 512;
            int isB = task >> 9, r2 = task & 511;
            int row = r2 >> 2, g = r2 & 3;
            uint32_t so = (uint32_t)(row * 64 + ((g ^ ((row >> 1) & 3)) << 4));
            if (!isB) cp16(stg + ST_AH + so, Ahp + (size_t)(m0 + row) * KDIM + k0 + g * 8);
            else      cp16(stg + ST_BH + so, Bhp + (size_t)(n0 + row) * KDIM + k0 + g * 8);
        }
        asm volatile("cp.async.commit_group;\n" ::: "memory");
    };

    load_chunk(0); load_chunk(1);

    for (int c = 0; c < NCH; c++) {
        const uint32_t stg = sb + (uint32_t)(c % 3) * STAGE;
        if (c < NCH - 1) asm volatile("cp.async.wait_group 1;\n" ::: "memory");
        else             asm volatile("cp.async.wait_group 0;\n" ::: "memory");
        __syncthreads();
        if (c + 2 < NCH) load_chunk(c + 2);

#pragma unroll
        for (int ks = 0; ks < 2; ks++) {
            const int g = ks * 2 + qhi;
            uint32_t a[2][4], b[4][2], t4[4];
#pragma unroll
            for (int p = 0; p < 2; p++) {
                ldm4(t4, stg + ST_BH + boff[p] + (uint32_t)((g ^ bxor[p]) << 4));
                b[2*p][0] = t4[0]; b[2*p+1][0] = t4[1]; b[2*p][1] = t4[2]; b[2*p+1][1] = t4[3];
            }
#pragma unroll
            for (int mt = 0; mt < 2; mt++)
                ldm4(a[mt], stg + ST_AH + aoff[mt] + (uint32_t)((g ^ axor[mt]) << 4));
#pragma unroll
            for (int mt = 0; mt < 2; mt++)
#pragma unroll
                for (int nt = 0; nt < 4; nt++) hmma(acc[mt][nt], a[mt], b[nt]);
        }
    }

#pragma unroll
    for (int mt = 0; mt < 2; mt++) {
        const int row = m0 + wm + mt * 16 + gid;
#pragma unroll
        for (int nt = 0; nt < 4; nt++) {
            const int col = n0 + wn + nt * 8 + tig * 2;
            const float bb0 = __ldg(bias + col), bb1 = __ldg(bias + col + 1);
            *(float2*)(Cf + (size_t)row * E_DIM + col) =
                make_float2(acc[mt][nt][0] + bb0, acc[mt][nt][1] + bb1);
            *(float2*)(Cf + (size_t)(row + 8) * E_DIM + col) =
                make_float2(acc[mt][nt][2] + bb0, acc[mt][nt][3] + bb1);
        }
    }
}

// ---------------------------------------------------------------------------
// Scores (R12 proven): 256 threads, warp 64x32, CTA 128x128, BK=64.
// ---------------------------------------------------------------------------
#define SC_AH 0
#define SC_BH 16384
#define SC_STAGE 32768
#define SC_SMEM (3 * SC_STAGE)        // 98304

__global__ __launch_bounds__(256, 2) void scores_hmma(
    const __half* __restrict__ Qh, const __half* __restrict__ Kh,
    float* __restrict__ Wp)
{
    const uint32_t sb = smem_u32(dynsmem);
    const int tid = threadIdx.x, wid = tid >> 5, lane = tid & 31;
    const int gid = lane >> 2, tig = lane & 3;
    const int q = lane >> 3, r8 = lane & 7, qlo = q & 1, qhi = q >> 1;
    const int wm = (wid & 1) * 64, wn = (wid >> 1) * 32;
    const int h = blockIdx.z >> 3, rs = blockIdx.z & 7;
    const int i0 = blockIdx.x * 128, j0 = blockIdx.y * 128;
    const int r_lo = rs * 32;

    int aoff[4], axor[4], boff[2], bxor[2];
#pragma unroll
    for (int mt = 0; mt < 4; mt++) {
        int rr = wm + mt * 16 + qlo * 8 + r8;
        aoff[mt] = rr * 128; axor[mt] = rr & 7;
    }
#pragma unroll
    for (int p = 0; p < 2; p++) {
        int rr = wn + p * 16 + qlo * 8 + r8;
        boff[p] = rr * 128; bxor[p] = rr & 7;
    }

    float acc[4][4][4];
#pragma unroll
    for (int mt = 0; mt < 4; mt++)
#pragma unroll
        for (int nt = 0; nt < 4; nt++)
#pragma unroll
            for (int e = 0; e < 4; e++) acc[mt][nt][e] = 0.0f;

    auto load_chunk = [&](int c) {
        const uint32_t stg = sb + (uint32_t)(c % 3) * SC_STAGE;
        const int r = r_lo + c;
#pragma unroll
        for (int t = 0; t < 8; t++) {
            int task = tid + t * 256;
            int isB = task >> 10, r2 = task & 1023;
            int row = r2 >> 3, g = r2 & 7;
            uint32_t so = (uint32_t)(row * 128 + ((g ^ (row & 7)) << 4));
            if (!isB)
                cp16(stg + SC_AH + so,
                     Qh + (size_t)(r * 256 + i0 + row) * E_DIM + h * DH + g * 8);
            else
                cp16(stg + SC_BH + so,
                     Kh + (size_t)(r * 256 + j0 + row) * E_DIM + h * DH + g * 8);
        }
        asm volatile("cp.async.commit_group;\n" ::: "memory");
    };

    load_chunk(0); load_chunk(1);

    for (int c = 0; c < 32; c++) {
        const uint32_t stg = sb + (uint32_t)(c % 3) * SC_STAGE;
        if (c < 31) asm volatile("cp.async.wait_group 1;\n" ::: "memory");
        else        asm volatile("cp.async.wait_group 0;\n" ::: "memory");
        __syncthreads();
        if (c + 2 < 32) load_chunk(c + 2);
#pragma unroll
        for (int ks = 0; ks < 4; ks++) {
            const int g = ks * 2 + qhi;
            uint32_t a[4], b[4][2], t4[4];
#pragma unroll
            for (int p = 0; p < 2; p++) {
                ldm4(t4, stg + SC_BH + boff[p] + (uint32_t)((g ^ bxor[p]) << 4));
                b[2*p][0] = t4[0]; b[2*p+1][0] = t4[1]; b[2*p][1] = t4[2]; b[2*p+1][1] = t4[3];
            }
#pragma unroll
            for (int mt = 0; mt < 4; mt++) {
                ldm4(a, stg + SC_AH + aoff[mt] + (uint32_t)((g ^ axor[mt]) << 4));
#pragma unroll
                for (int nt = 0; nt < 4; nt++) hmma(acc[mt][nt], a, b[nt]);
            }
        }
    }

    float* base = Wp + (size_t)blockIdx.z * 65536;
#pragma unroll
    for (int mt = 0; mt < 4; mt++) {
        const int i = i0 + wm + mt * 16 + gid;
#pragma unroll
        for (int nt = 0; nt < 4; nt++) {
            const int j = j0 + wn + nt * 8 + tig * 2;
            *(float2*)(base + (size_t)i * 256 + j)       = make_float2(acc[mt][nt][0], acc[mt][nt][1]);
            *(float2*)(base + (size_t)(i + 8) * 256 + j) = make_float2(acc[mt][nt][2], acc[mt][nt][3]);
        }
    }
}

// ---------------------------------------------------------------------------
// Reduce partials + SCALE + softmax (unchanged)
// ---------------------------------------------------------------------------
__global__ __launch_bounds__(256) void softmax_reduce(
    const float* __restrict__ Wp, float* __restrict__ P,
    __half* __restrict__ Ph)
{
    __shared__ float red[8];
    const int row = blockIdx.x;
    const int h = row >> 8;
    const int tid = threadIdx.x;

    float v = 0.0f;
#pragma unroll
    for (int rs = 0; rs < 8; rs++)
        v += Wp[((size_t)(h * 8 + rs)) * 65536 + (size_t)(row & 255) * 256 + tid];
    v *= SCALE;

    float m = v;
#pragma unroll
    for (int o = 16; o > 0; o >>= 1) m = fmaxf(m, __shfl_xor_sync(0xffffffffu, m, o));
    if ((tid & 31) == 0) red[tid >> 5] = m;
    __syncthreads();
    float m_all = red[0];
#pragma unroll
    for (int w = 1; w < 8; w++) m_all = fmaxf(m_all, red[w]);
    const float e = __expf(v - m_all);
    float s = e;
#pragma unroll
    for (int o = 16; o > 0; o >>= 1) s += __shfl_xor_sync(0xffffffffu, s, o);
    __syncthreads();
    if ((tid & 31) == 0) red[tid >> 5] = s;
    __syncthreads();
    float s_all = 0.0f;
#pragma unroll
    for (int w = 0; w < 8; w++) s_all += red[w];

    const float p = e / s_all;
    const size_t idx = (size_t)row * 256 + tid;
    P[idx] = p;
    Ph[idx] = __float2half_rn(p);
}

// ---------------------------------------------------------------------------
// Context (fp16), r-blocked x8 (R13 proven, launch_bounds (256,2))
// ---------------------------------------------------------------------------
#define CT_PH 0
#define CT_VH 8192
#define CT_STAGE 12288
#define CT_SMEM (2 * CT_STAGE)        // 24576

__global__ __launch_bounds__(256, 2) void context_hmma(
    const __half* __restrict__ Ph, const __half* __restrict__ Vh,
    __half* __restrict__ Oh)
{
    const uint32_t sb = smem_u32(dynsmem);
    const int tid = threadIdx.x, wid = tid >> 5, lane = tid & 31;
    const int gid = lane >> 2, tig = lane & 3;
    const int q = lane >> 3, r8 = lane & 7, qlo = q & 1, qhi = q >> 1;
    const int wmi = (wid >> 1) * 32, wnd = (wid & 1) * 32;
    const int i0 = blockIdx.x * 128, r_base = blockIdx.y * 8, h = blockIdx.z;

    int aoff[2], axor[2];
#pragma unroll
    for (int mt = 0; mt < 2; mt++) {
        int rr = wmi + mt * 16 + qlo * 8 + r8;
        aoff[mt] = rr * 64; axor[mt] = (rr >> 1) & 3;
    }
    int gB[2];
#pragma unroll
    for (int p = 0; p < 2; p++) gB[p] = (wnd >> 3) + p * 2 + qhi;
    const int jbase = qlo * 8 + r8;

    float acc[2][4][4];
#pragma unroll
    for (int mt = 0; mt < 2; mt++)
#pragma unroll
        for (int nt = 0; nt < 4; nt++)
#pragma unroll
            for (int e = 0; e < 4; e++) acc[mt][nt][e] = 0.0f;

    auto load_chunk = [&](int cc) {
        const uint32_t stg = sb + (uint32_t)(cc & 1) * CT_STAGE;
        const int j0 = (cc & 7) * 32;
        const int r = r_base + (cc >> 3);
#pragma unroll
        for (int t = 0; t < 3; t++) {
            int task = tid + t * 256;
            if (task < 512) {
                int row = task >> 2, g = task & 3;
                cp16(stg + CT_PH + (uint32_t)(row * 64 + ((g ^ ((row >> 1) & 3)) << 4)),
                     Ph + (size_t)h * 65536 + (size_t)(i0 + row) * 256 + j0 + g * 8);
            } else {
                int t2 = task - 512;
                int row = t2 >> 3, g = t2 & 7;
                cp16(stg + CT_VH + (uint32_t)(row * 128 + ((g ^ (row & 7)) << 4)),
                     Vh + (size_t)(r * 256 + j0 + row) * E_DIM + h * DH + g * 8);
            }
        }
        asm volatile("cp.async.commit_group;\n" ::: "memory");
    };

    load_chunk(0); load_chunk(1);

    for (int cc = 0; cc < 64; cc++) {
        const uint32_t stg = sb + (uint32_t)(cc & 1) * CT_STAGE;
        if (cc == 63) asm volatile("cp.async.wait_group 0;\n" ::: "memory");
        else          asm volatile("cp.async.wait_group 1;\n" ::: "memory");
        __syncthreads();
#pragma unroll
        for (int ks = 0; ks < 2; ks++) {
            const int ga = ks * 2 + qhi;
            const int jrow = ks * 16 + jbase;
            uint32_t a[2][4], b[4][2], t4[4];
#pragma unroll
            for (int p = 0; p < 2; p++) {
                ldm4t(t4, stg + CT_VH + (uint32_t)(jrow * 128 + ((gB[p] ^ (jrow & 7)) << 4)));
                b[2*p][0] = t4[0]; b[2*p][1] = t4[1]; b[2*p+1][0] = t4[2]; b[2*p+1][1] = t4[3];
            }
#pragma unroll
            for (int mt = 0; mt < 2; mt++)
                ldm4(a[mt], stg + CT_PH + aoff[mt] + (uint32_t)((ga ^ axor[mt]) << 4));
#pragma unroll
            for (int mt = 0; mt < 2; mt++)
#pragma unroll
                for (int nt = 0; nt < 4; nt++) hmma(acc[mt][nt], a[mt], b[nt]);
        }

        if ((cc & 7) == 7) {
            const int r = r_base + (cc >> 3);
#pragma unroll
            for (int mt = 0; mt < 2; mt++) {
                const int row_i = i0 + wmi + mt * 16 + gid;
#pragma unroll
                for (int nt = 0; nt < 4; nt++) {
                    const int col = wnd + nt * 8 + tig * 2;
                    size_t i0b = (size_t)(r * 256 + row_i) * E_DIM + h * DH + col;
                    size_t i1b = (size_t)(r * 256 + row_i + 8) * E_DIM + h * DH + col;
                    *(uint32_t*)(Oh + i0b) = pack_h(acc[mt][nt][0], acc[mt][nt][1]);
                    *(uint32_t*)(Oh + i1b) = pack_h(acc[mt][nt][2], acc[mt][nt][3]);
#pragma unroll
                    for (int e = 0; e < 4; e++) acc[mt][nt][e] = 0.0f;
                }
            }
        }
        __syncthreads();
        if (cc + 2 < 64) load_chunk(cc + 2);
    }
}

// ---------------- launch ----------------
extern "C" void kernel_launch(void* const* d_in, const int* in_sizes, int n_in,
                              void* d_out, int out_size)
{
    const float* x  = (const float*)d_in[0];
    const float* Wq = (const float*)d_in[1];
    const float* bq = (const float*)d_in[2];
    const float* Wk = (const float*)d_in[3];
    const float* bk = (const float*)d_in[4];
    const float* Wv = (const float*)d_in[5];
    const float* bv = (const float*)d_in[6];
    const float* Wo = (const float*)d_in[7];
    const float* bo = (const float*)d_in[8];

    float* out_y = (float*)d_out;
    float* out_p = (float*)d_out + PROJ_ELEMS;

    __half *Ah, *Qh, *Kh, *Vh, *Wh, *Ph;
    float* Wp;
    cudaGetSymbolAddress((void**)&Ah, g_Ah);
    cudaGetSymbolAddress((void**)&Qh, g_Qh);
    cudaGetSymbolAddress((void**)&Kh, g_Kh);
    cudaGetSymbolAddress((void**)&Vh, g_Vh);
    cudaGetSymbolAddress((void**)&Wh, g_Wq4);
    cudaGetSymbolAddress((void**)&Ph, g_Ph);
    cudaGetSymbolAddress((void**)&Wp, g_Wpart);

    cudaFuncSetAttribute(gemm_qkv,     cudaFuncAttributeMaxDynamicSharedMemorySize, GEMM_SMEM);
    cudaFuncSetAttribute(gemm_out,     cudaFuncAttributeMaxDynamicSharedMemorySize, GEMM_SMEM);
    cudaFuncSetAttribute(scores_hmma,  cudaFuncAttributeMaxDynamicSharedMemorySize, SC_SMEM);
    cudaFuncSetAttribute(context_hmma, cudaFuncAttributeMaxDynamicSharedMemorySize, CT_SMEM);

    const int nx = (int)PROJ_ELEMS, nw = (int)WSZ;
    split1_kernel<<<nx / 1024, 256>>>(x, Ah, nx);
    split4w_kernel<<<dim3(nw / 1024, 4), 256>>>(Wq, Wk, Wv, Wo, Wh);

    gemm_qkv<<<dim3(18, TOK / 128), 512, GEMM_SMEM>>>(Ah, Wh, bq, bk, bv, Qh, Kh, Vh);

    scores_hmma<<<dim3(2, 2, 96), 256, SC_SMEM>>>(Qh, Kh, Wp);
    softmax_reduce<<<H_HEADS * C_DIM, 256>>>(Wp, out_p, Ph);
    context_hmma<<<dim3(2, 32, 12), 256, CT_SMEM>>>(Ph, Vh, Ah);

    gemm_out<<<dim3(6, TOK / 128), 512, GEMM_SMEM>>>(Ah, Wh + 3 * WSZ, bo, out_y);
}